// round 1
// baseline (speedup 1.0000x reference)
#include <cuda_runtime.h>
#include <cuda_bf16.h>
#include <math.h>

// Shapes (fixed by the problem)
#define Ln 4
#define Dn 512
#define Hn 2048
#define Vn 32000
#define Bn 2
#define Tn 2048
#define NTOK (Bn*Tn)   // 4096

// ---------------- scratch (device globals; allocation-free) ----------------
__device__ float g_X [NTOK * Dn];          // residual stream
__device__ float g_Y [NTOK * Dn];          // layernorm output / values
__device__ float g_XG[NTOK * Dn];          // Y @ G
__device__ float g_Dv[NTOK];               // diag(S)
__device__ float g_S [(long long)Bn * Tn * Tn];  // scores / probs (33.5 MB)
__device__ float g_U [(long long)NTOK * Hn];     // FFN hidden (33.5 MB)

// ---------------- SGEMM: C[M,N] = A[M,K] @ B (opt. B^T), epilogues ---------
// EPI: 0 store, 1 +bias, 2 gelu(+bias), 3 C+=acc, 4 C+=acc+bias
#define TM 128
#define TN 128
#define TK 16

template<bool TRANSB, int EPI>
__global__ __launch_bounds__(256, 2)
void sgemm(const float* __restrict__ A, const float* __restrict__ B,
           float* __restrict__ C, const float* __restrict__ bias,
           int M, int N, int K, long long sA, long long sB, long long sC)
{
    __shared__ float As[TK][TM];
    __shared__ float Bs[TK][TN];
    const int tid = threadIdx.x;
    const int tx = tid & 15, ty = tid >> 4;
    const int m0 = blockIdx.y * TM;
    const int n0 = blockIdx.x * TN;
    A += (long long)blockIdx.z * sA;
    B += (long long)blockIdx.z * sB;
    C += (long long)blockIdx.z * sC;

    float acc[8][8];
#pragma unroll
    for (int i = 0; i < 8; i++)
#pragma unroll
        for (int j = 0; j < 8; j++) acc[i][j] = 0.f;

    for (int k0 = 0; k0 < K; k0 += TK) {
        // A tile: 128 rows x 16 k (K-contiguous)
#pragma unroll
        for (int t = tid; t < 512; t += 256) {
            int r = t >> 2, q = t & 3;
            float4 v = *reinterpret_cast<const float4*>(
                &A[(long long)(m0 + r) * K + k0 + q * 4]);
            As[q*4+0][r] = v.x; As[q*4+1][r] = v.y;
            As[q*4+2][r] = v.z; As[q*4+3][r] = v.w;
        }
        if (TRANSB) {
            // B is (N,K) row-major: Bs[k][n] = B[n*K + k]
#pragma unroll
            for (int t = tid; t < 512; t += 256) {
                int r = t >> 2, q = t & 3;
                float4 v = *reinterpret_cast<const float4*>(
                    &B[(long long)(n0 + r) * K + k0 + q * 4]);
                Bs[q*4+0][r] = v.x; Bs[q*4+1][r] = v.y;
                Bs[q*4+2][r] = v.z; Bs[q*4+3][r] = v.w;
            }
        } else {
            // B is (K,N) row-major: Bs[k][n] = B[k*N + n]
#pragma unroll
            for (int t = tid; t < 512; t += 256) {
                int k = t >> 5, nq = t & 31;
                float4 v = *reinterpret_cast<const float4*>(
                    &B[(long long)(k0 + k) * N + n0 + nq * 4]);
                *reinterpret_cast<float4*>(&Bs[k][nq * 4]) = v;
            }
        }
        __syncthreads();
#pragma unroll
        for (int kk = 0; kk < TK; kk++) {
            float a[8], bv[8];
            *reinterpret_cast<float4*>(&a[0])  = *reinterpret_cast<const float4*>(&As[kk][ty*8]);
            *reinterpret_cast<float4*>(&a[4])  = *reinterpret_cast<const float4*>(&As[kk][ty*8+4]);
            *reinterpret_cast<float4*>(&bv[0]) = *reinterpret_cast<const float4*>(&Bs[kk][tx*8]);
            *reinterpret_cast<float4*>(&bv[4]) = *reinterpret_cast<const float4*>(&Bs[kk][tx*8+4]);
#pragma unroll
            for (int i = 0; i < 8; i++)
#pragma unroll
                for (int j = 0; j < 8; j++) acc[i][j] += a[i] * bv[j];
        }
        __syncthreads();
    }

#pragma unroll
    for (int i = 0; i < 8; i++) {
        long long row = m0 + ty * 8 + i;
        float* crow = &C[row * (long long)N + n0 + tx * 8];
#pragma unroll
        for (int j = 0; j < 8; j++) {
            float v = acc[i][j];
            if (EPI == 1 || EPI == 2 || EPI == 4) v += bias[n0 + tx * 8 + j];
            if (EPI == 2) v = 0.5f * v * (1.0f + erff(v * 0.70710678118654752f));
            if (EPI == 3 || EPI == 4) v += crow[j];
            crow[j] = v;
        }
    }
}

// ---------------- embedding gather ----------------
__global__ void embed_kernel(const int* __restrict__ ids,
                             const float* __restrict__ emb,
                             float* __restrict__ X)
{
    long long i = (long long)blockIdx.x * 256 + threadIdx.x;  // < NTOK*Dn
    int tok = (int)(i >> 9);
    int d   = (int)(i & 511);
    X[i] = emb[(long long)ids[tok] * Dn + d];
}

// ---------------- layernorm (one token per block, 256 threads) -------------
__global__ void layernorm_kernel(const float* __restrict__ in,
                                 float* __restrict__ out,
                                 const float* __restrict__ gamma,
                                 const float* __restrict__ beta)
{
    int tok = blockIdx.x;
    const float* x = in + (long long)tok * Dn;
    int t = threadIdx.x;
    float v0 = x[t], v1 = x[t + 256];
    float s = v0 + v1, s2 = v0 * v0 + v1 * v1;
#pragma unroll
    for (int o = 16; o; o >>= 1) {
        s  += __shfl_xor_sync(0xffffffffu, s,  o);
        s2 += __shfl_xor_sync(0xffffffffu, s2, o);
    }
    __shared__ float ss[8], ss2[8];
    int w = t >> 5, lane = t & 31;
    if (lane == 0) { ss[w] = s; ss2[w] = s2; }
    __syncthreads();
    if (w == 0) {
        s  = (lane < 8) ? ss[lane]  : 0.f;
        s2 = (lane < 8) ? ss2[lane] : 0.f;
#pragma unroll
        for (int o = 4; o; o >>= 1) {
            s  += __shfl_xor_sync(0xffffffffu, s,  o);
            s2 += __shfl_xor_sync(0xffffffffu, s2, o);
        }
        if (lane == 0) { ss[0] = s; ss2[0] = s2; }
    }
    __syncthreads();
    float mu  = ss[0] * (1.f / Dn);
    float var = ss2[0] * (1.f / Dn) - mu * mu;
    float inv = rsqrtf(var + 1e-5f);
    float* o = out + (long long)tok * Dn;
    o[t]       = (v0 - mu) * inv * gamma[t]       + beta[t];
    o[t + 256] = (v1 - mu) * inv * gamma[t + 256] + beta[t + 256];
}

// ---------------- diag(S) -> d ----------------
__global__ void diag_kernel(const float* __restrict__ S, float* __restrict__ d)
{
    int i = blockIdx.x * 256 + threadIdx.x;   // < NTOK
    int b = i / Tn, t = i % Tn;
    d[i] = S[(long long)b * Tn * Tn + (long long)t * (Tn + 1)];
}

// ---------------- row softmax of (2*S - d[j]) in place ----------------
__global__ void softmax_kernel(float* __restrict__ S, const float* __restrict__ d)
{
    int b = blockIdx.y, t = blockIdx.x;
    float* row = S + (long long)b * Tn * Tn + (long long)t * Tn;
    const float* db = d + b * Tn;
    int tid = threadIdx.x;
    float v[8];
    float mx = -1e30f;
#pragma unroll
    for (int r = 0; r < 8; r++) {
        int j = tid + r * 256;
        v[r] = 2.f * row[j] - db[j];
        mx = fmaxf(mx, v[r]);
    }
    __shared__ float red[8];
#pragma unroll
    for (int o = 16; o; o >>= 1) mx = fmaxf(mx, __shfl_xor_sync(0xffffffffu, mx, o));
    int w = tid >> 5, lane = tid & 31;
    if (lane == 0) red[w] = mx;
    __syncthreads();
    if (w == 0) {
        mx = (lane < 8) ? red[lane] : -1e30f;
#pragma unroll
        for (int o = 4; o; o >>= 1) mx = fmaxf(mx, __shfl_xor_sync(0xffffffffu, mx, o));
        if (lane == 0) red[0] = mx;
    }
    __syncthreads();
    mx = red[0];
    float sum = 0.f;
#pragma unroll
    for (int r = 0; r < 8; r++) { v[r] = expf(v[r] - mx); sum += v[r]; }
    __syncthreads();
#pragma unroll
    for (int o = 16; o; o >>= 1) sum += __shfl_xor_sync(0xffffffffu, sum, o);
    if (lane == 0) red[w] = sum;
    __syncthreads();
    if (w == 0) {
        sum = (lane < 8) ? red[lane] : 0.f;
#pragma unroll
        for (int o = 4; o; o >>= 1) sum += __shfl_xor_sync(0xffffffffu, sum, o);
        if (lane == 0) red[0] = sum;
    }
    __syncthreads();
    float inv = 1.f / red[0];
#pragma unroll
    for (int r = 0; r < 8; r++) row[tid + r * 256] = v[r] * inv;
}

// ---------------- launch ----------------
extern "C" void kernel_launch(void* const* d_in, const int* in_sizes, int n_in,
                              void* d_out, int out_size)
{
    const int*   ids   = (const int*)  d_in[0];
    const float* emb   = (const float*)d_in[1];
    const float* g     = (const float*)d_in[2];
    const float* W1    = (const float*)d_in[3];
    const float* b1    = (const float*)d_in[4];
    const float* W2    = (const float*)d_in[5];
    const float* b2    = (const float*)d_in[6];
    const float* ln1s  = (const float*)d_in[7];
    const float* ln1b  = (const float*)d_in[8];
    const float* ln2s  = (const float*)d_in[9];
    const float* ln2b  = (const float*)d_in[10];
    const float* lnfs  = (const float*)d_in[11];
    const float* lnfb  = (const float*)d_in[12];
    const float* headw = (const float*)d_in[13];
    const float* headb = (const float*)d_in[14];
    float* out = (float*)d_out;

    float *pX, *pY, *pXG, *pD, *pS, *pU;
    cudaGetSymbolAddress((void**)&pX,  g_X);
    cudaGetSymbolAddress((void**)&pY,  g_Y);
    cudaGetSymbolAddress((void**)&pXG, g_XG);
    cudaGetSymbolAddress((void**)&pD,  g_Dv);
    cudaGetSymbolAddress((void**)&pS,  g_S);
    cudaGetSymbolAddress((void**)&pU,  g_U);

    // x = embed[ids]
    embed_kernel<<<(NTOK * Dn) / 256, 256>>>(ids, emb, pX);

    for (int l = 0; l < Ln; l++) {
        // y = ln1(x)
        layernorm_kernel<<<NTOK, 256>>>(pX, pY, ln1s + l * Dn, ln1b + l * Dn);
        // xg = y @ G[l]                 (4096,512,512)
        sgemm<false, 0><<<dim3(Dn / TN, NTOK / TM, 1), 256>>>(
            pY, g + (long long)l * Dn * Dn, pXG, nullptr,
            NTOK, Dn, Dn, 0, 0, 0);
        // S_b = XG_b @ Y_b^T            (2048,2048,512) x2 batches
        sgemm<true, 0><<<dim3(Tn / TN, Tn / TM, Bn), 256>>>(
            pXG, pY, pS, nullptr,
            Tn, Tn, Dn, (long long)Tn * Dn, (long long)Tn * Dn, (long long)Tn * Tn);
        // d = diag(S)
        diag_kernel<<<NTOK / 256, 256>>>(pS, pD);
        // P = softmax_j(2 S - d_j)  (in place)
        softmax_kernel<<<dim3(Tn, Bn), 256>>>(pS, pD);
        // x += P_b @ Y_b                (2048,512,2048) x2
        sgemm<false, 3><<<dim3(Dn / TN, Tn / TM, Bn), 256>>>(
            pS, pY, pX, nullptr,
            Tn, Dn, Tn, (long long)Tn * Tn, (long long)Tn * Dn, (long long)Tn * Dn);
        // h = ln2(x)
        layernorm_kernel<<<NTOK, 256>>>(pX, pY, ln2s + l * Dn, ln2b + l * Dn);
        // u = gelu(h @ W1 + b1)         (4096,2048,512)
        sgemm<false, 2><<<dim3(Hn / TN, NTOK / TM, 1), 256>>>(
            pY, W1 + (long long)l * Dn * Hn, pU, b1 + l * Hn,
            NTOK, Hn, Dn, 0, 0, 0);
        // x += u @ W2 + b2              (4096,512,2048)
        sgemm<false, 4><<<dim3(Dn / TN, NTOK / TM, 1), 256>>>(
            pU, W2 + (long long)l * Hn * Dn, pX, b2 + l * Dn,
            NTOK, Dn, Hn, 0, 0, 0);
    }
    // y = lnf(x)
    layernorm_kernel<<<NTOK, 256>>>(pX, pY, lnfs, lnfb);
    // out = y @ head_w + head_b        (4096,32000,512)
    sgemm<false, 1><<<dim3(Vn / TN, NTOK / TM, 1), 256>>>(
        pY, headw, out, headb,
        NTOK, Vn, Dn, 0, 0, 0);
}